// round 1
// baseline (speedup 1.0000x reference)
#include <cuda_runtime.h>
#include <math.h>

#define B_ 4
#define T_ 2048
#define E_ 1024
#define H_ 16
#define D_ 64

// Scratch (device globals: allocation-free).
// g_proj[0] = xq (pre-scaled by 1/sqrt(E)), g_proj[1] = xk, g_proj[2] = xv,
// each laid out [B,H,T,D]. g_attn = concatenated heads [B,T,E].
__device__ float g_proj[3][(size_t)B_ * H_ * T_ * D_];
__device__ float g_attn[(size_t)B_ * T_ * E_];

// ---------------------------------------------------------------------------
// QKV projection: for each (which, b, h): out[T,D] = X_b[T,E] @ W_h[E,D]
// grid (T/128, B*H, 3), 256 threads, 128x64 tile, BK=16, 8x4 micro-tile.
// ---------------------------------------------------------------------------
__global__ __launch_bounds__(256) void proj_kernel(
    const float* __restrict__ q, const float* __restrict__ k,
    const float* __restrict__ v, const float* __restrict__ Wq,
    const float* __restrict__ Wk, const float* __restrict__ Wv)
{
    __shared__ float As[128][16];   // [row][k]
    __shared__ float Ws[16][64];    // [k][n] (natural W layout)

    const int which = blockIdx.z;
    const int bh    = blockIdx.y;
    const int b     = bh >> 4;
    const int h     = bh & 15;
    const int t0    = blockIdx.x * 128;

    const float* X = (which == 0 ? q : (which == 1 ? k : v)) + (size_t)b * T_ * E_;
    const float* W = (which == 0 ? Wq : (which == 1 ? Wk : Wv)) + (size_t)h * E_ * D_;
    float* out = &g_proj[which][((size_t)bh * T_ + t0) * D_];

    const int tid = threadIdx.x;
    const int ty  = tid >> 4;
    const int tx  = tid & 15;

    float acc[8][4];
#pragma unroll
    for (int i = 0; i < 8; i++)
#pragma unroll
        for (int j = 0; j < 4; j++) acc[i][j] = 0.f;

    for (int e0 = 0; e0 < E_; e0 += 16) {
        // A tile 128x16 (float4, coalesced)
#pragma unroll
        for (int u = 0; u < 2; u++) {
            int idx = tid + u * 256;          // 512 float4 chunks
            int row = idx >> 2;
            int kq  = idx & 3;
            *(float4*)&As[row][kq * 4] =
                *(const float4*)&X[(size_t)(t0 + row) * E_ + e0 + kq * 4];
        }
        // W tile 16x64 (float4, natural layout)
        {
            int row = tid >> 4;
            int col = (tid & 15) * 4;
            *(float4*)&Ws[row][col] =
                *(const float4*)&W[(size_t)(e0 + row) * D_ + col];
        }
        __syncthreads();

#pragma unroll
        for (int kk = 0; kk < 16; kk++) {
            float a[8];
#pragma unroll
            for (int i = 0; i < 8; i++) a[i] = As[ty * 8 + i][kk];
            float4 b4 = *(float4*)&Ws[kk][tx * 4];
#pragma unroll
            for (int i = 0; i < 8; i++) {
                acc[i][0] += a[i] * b4.x;
                acc[i][1] += a[i] * b4.y;
                acc[i][2] += a[i] * b4.z;
                acc[i][3] += a[i] * b4.w;
            }
        }
        __syncthreads();
    }

    // fold the 1/sqrt(E) attention scale into xq
    const float scale = (which == 0) ? 0.03125f : 1.0f;
#pragma unroll
    for (int i = 0; i < 8; i++) {
        float4 st;
        st.x = acc[i][0] * scale;
        st.y = acc[i][1] * scale;
        st.z = acc[i][2] * scale;
        st.w = acc[i][3] * scale;
        *(float4*)&out[(size_t)(ty * 8 + i) * D_ + tx * 4] = st;
    }
}

// ---------------------------------------------------------------------------
// Causal flash attention: per (b,h), 64-query tile per block, streams 64-key
// tiles with online softmax. grid (T/64, B*H), 256 threads, 4x4 micro-tiles.
// Writes concatenated-head output straight into [B,T,E].
// ---------------------------------------------------------------------------
__global__ __launch_bounds__(256) void flash_kernel()
{
    extern __shared__ float sm[];
    float* Qs = sm;                 // [64][64]  (r,d)
    float* Ks = Qs + 64 * 64;       // [64][65]  (c,d)  padded
    float* Vs = Ks + 64 * 65;       // [64][64]  (s,c)
    float* Ps = Vs + 64 * 64;       // [64][68]  (r,s)  padded, float4-aligned

    const int bh = blockIdx.y;
    const int qt = blockIdx.x;

    const float* Q = &g_proj[0][((size_t)bh * T_ + (size_t)qt * 64) * D_];
    const float* K = &g_proj[1][(size_t)bh * T_ * D_];
    const float* V = &g_proj[2][(size_t)bh * T_ * D_];

    const int tid = threadIdx.x;
    const int ty  = tid >> 4;
    const int tx  = tid & 15;

    // Load Q tile once (float4, coalesced)
#pragma unroll
    for (int u = 0; u < 4; u++) {
        int idx = tid + u * 256;
        int r  = idx >> 4;
        int c4 = (idx & 15) * 4;
        *(float4*)&Qs[r * 64 + c4] = *(const float4*)&Q[(size_t)r * D_ + c4];
    }

    float O[4][4];
    float m_r[4], l_r[4];
#pragma unroll
    for (int i = 0; i < 4; i++) {
        m_r[i] = -INFINITY;
        l_r[i] = 0.f;
#pragma unroll
        for (int j = 0; j < 4; j++) O[i][j] = 0.f;
    }

    for (int kt = 0; kt <= qt; kt++) {
        __syncthreads();   // prev tile's PV reads done; also orders Qs load on iter 0
        // K tile -> Ks[c][d], stride 65 (scalar stores; 2-way worst case)
#pragma unroll
        for (int u = 0; u < 4; u++) {
            int idx = tid + u * 256;
            int c  = idx >> 4;
            int d4 = (idx & 15) * 4;
            float4 kv = *(const float4*)&K[((size_t)kt * 64 + c) * D_ + d4];
            Ks[c * 65 + d4 + 0] = kv.x;
            Ks[c * 65 + d4 + 1] = kv.y;
            Ks[c * 65 + d4 + 2] = kv.z;
            Ks[c * 65 + d4 + 3] = kv.w;
        }
        // V tile direct copy
#pragma unroll
        for (int u = 0; u < 4; u++) {
            int idx = tid + u * 256;
            int s  = idx >> 4;
            int c4 = (idx & 15) * 4;
            *(float4*)&Vs[s * 64 + c4] =
                *(const float4*)&V[((size_t)kt * 64 + s) * D_ + c4];
        }
        __syncthreads();

        // S = Q @ K^T (xq already carries 1/sqrt(E))
        float S[4][4];
#pragma unroll
        for (int i = 0; i < 4; i++)
#pragma unroll
            for (int j = 0; j < 4; j++) S[i][j] = 0.f;

#pragma unroll 8
        for (int d = 0; d < 64; d++) {
            float a0 = Qs[(4 * ty + 0) * 64 + d];
            float a1 = Qs[(4 * ty + 1) * 64 + d];
            float a2 = Qs[(4 * ty + 2) * 64 + d];
            float a3 = Qs[(4 * ty + 3) * 64 + d];
            float b0 = Ks[(4 * tx + 0) * 65 + d];
            float b1 = Ks[(4 * tx + 1) * 65 + d];
            float b2 = Ks[(4 * tx + 2) * 65 + d];
            float b3 = Ks[(4 * tx + 3) * 65 + d];
            S[0][0] += a0 * b0; S[0][1] += a0 * b1; S[0][2] += a0 * b2; S[0][3] += a0 * b3;
            S[1][0] += a1 * b0; S[1][1] += a1 * b1; S[1][2] += a1 * b2; S[1][3] += a1 * b3;
            S[2][0] += a2 * b0; S[2][1] += a2 * b1; S[2][2] += a2 * b2; S[2][3] += a2 * b3;
            S[3][0] += a3 * b0; S[3][1] += a3 * b1; S[3][2] += a3 * b2; S[3][3] += a3 * b3;
        }

        // causal mask inside the diagonal tile (local indices: same tile offset)
        if (kt == qt) {
#pragma unroll
            for (int i = 0; i < 4; i++)
#pragma unroll
                for (int j = 0; j < 4; j++)
                    if (4 * tx + j > 4 * ty + i) S[i][j] = -INFINITY;
        }

        // online softmax (row groups = 16 contiguous lanes; shfl_xor <=8 stays in-group)
#pragma unroll
        for (int i = 0; i < 4; i++) {
            float tm = fmaxf(fmaxf(S[i][0], S[i][1]), fmaxf(S[i][2], S[i][3]));
#pragma unroll
            for (int off = 8; off > 0; off >>= 1)
                tm = fmaxf(tm, __shfl_xor_sync(0xffffffffu, tm, off));
            float mn = fmaxf(m_r[i], tm);
            float al = __expf(m_r[i] - mn);   // exp(-inf)=0 on first tile
#pragma unroll
            for (int j = 0; j < 4; j++) S[i][j] = __expf(S[i][j] - mn);
            float psum = S[i][0] + S[i][1] + S[i][2] + S[i][3];
#pragma unroll
            for (int off = 8; off > 0; off >>= 1)
                psum += __shfl_xor_sync(0xffffffffu, psum, off);
            l_r[i] = l_r[i] * al + psum;
            m_r[i] = mn;
#pragma unroll
            for (int j = 0; j < 4; j++) O[i][j] *= al;
        }

        // stage P (float4 stores, conflict-free)
#pragma unroll
        for (int i = 0; i < 4; i++) {
            float4 pv;
            pv.x = S[i][0]; pv.y = S[i][1]; pv.z = S[i][2]; pv.w = S[i][3];
            *(float4*)&Ps[(4 * ty + i) * 68 + 4 * tx] = pv;
        }
        __syncthreads();

        // O += P @ V
#pragma unroll 8
        for (int s = 0; s < 64; s++) {
            float a0 = Ps[(4 * ty + 0) * 68 + s];
            float a1 = Ps[(4 * ty + 1) * 68 + s];
            float a2 = Ps[(4 * ty + 2) * 68 + s];
            float a3 = Ps[(4 * ty + 3) * 68 + s];
            float4 b4 = *(float4*)&Vs[s * 64 + 4 * tx];
            O[0][0] += a0 * b4.x; O[0][1] += a0 * b4.y; O[0][2] += a0 * b4.z; O[0][3] += a0 * b4.w;
            O[1][0] += a1 * b4.x; O[1][1] += a1 * b4.y; O[1][2] += a1 * b4.z; O[1][3] += a1 * b4.w;
            O[2][0] += a2 * b4.x; O[2][1] += a2 * b4.y; O[2][2] += a2 * b4.z; O[2][3] += a2 * b4.w;
            O[3][0] += a3 * b4.x; O[3][1] += a3 * b4.y; O[3][2] += a3 * b4.z; O[3][3] += a3 * b4.w;
        }
    }

    // epilogue: normalize, scatter into concatenated-head layout [B,T,E]
    const int b = bh >> 4;
    const int h = bh & 15;
    float* outp = &g_attn[((size_t)b * T_ + (size_t)qt * 64) * E_ + h * D_];
#pragma unroll
    for (int i = 0; i < 4; i++) {
        float inv = 1.f / l_r[i];
        float4 st;
        st.x = O[i][0] * inv;
        st.y = O[i][1] * inv;
        st.z = O[i][2] * inv;
        st.w = O[i][3] * inv;
        *(float4*)&outp[(size_t)(4 * ty + i) * E_ + 4 * tx] = st;
    }
}

// ---------------------------------------------------------------------------
// Output projection: out[M,E] = g_attn[M,E] @ Wp^T + bp, M = B*T.
// grid (M/128, E/64), 256 threads. Wp accessed transposed (row n is K-vector).
// ---------------------------------------------------------------------------
__global__ __launch_bounds__(256) void outproj_kernel(
    const float* __restrict__ Wp, const float* __restrict__ bp,
    float* __restrict__ out)
{
    __shared__ float As[128][16];
    __shared__ float Ws[16][64];    // [k][n], filled transposed from Wp

    const int m0 = blockIdx.x * 128;
    const int n0 = blockIdx.y * 64;
    const int tid = threadIdx.x;
    const int ty  = tid >> 4;
    const int tx  = tid & 15;
    const float* A = g_attn;

    float acc[8][4];
#pragma unroll
    for (int i = 0; i < 8; i++)
#pragma unroll
        for (int j = 0; j < 4; j++) acc[i][j] = 0.f;

    for (int e0 = 0; e0 < E_; e0 += 16) {
#pragma unroll
        for (int u = 0; u < 2; u++) {
            int idx = tid + u * 256;
            int row = idx >> 2;
            int kq  = idx & 3;
            *(float4*)&As[row][kq * 4] =
                *(const float4*)&A[(size_t)(m0 + row) * E_ + e0 + kq * 4];
        }
        {
            int n  = tid >> 2;      // 0..63
            int kq = tid & 3;       // 0..3
            float4 wv = *(const float4*)&Wp[(size_t)(n0 + n) * E_ + e0 + kq * 4];
            Ws[kq * 4 + 0][n] = wv.x;
            Ws[kq * 4 + 1][n] = wv.y;
            Ws[kq * 4 + 2][n] = wv.z;
            Ws[kq * 4 + 3][n] = wv.w;
        }
        __syncthreads();

#pragma unroll
        for (int kk = 0; kk < 16; kk++) {
            float a[8];
#pragma unroll
            for (int i = 0; i < 8; i++) a[i] = As[ty * 8 + i][kk];
            float4 b4 = *(float4*)&Ws[kk][tx * 4];
#pragma unroll
            for (int i = 0; i < 8; i++) {
                acc[i][0] += a[i] * b4.x;
                acc[i][1] += a[i] * b4.y;
                acc[i][2] += a[i] * b4.z;
                acc[i][3] += a[i] * b4.w;
            }
        }
        __syncthreads();
    }

    float4 bias = *(const float4*)&bp[n0 + tx * 4];
#pragma unroll
    for (int i = 0; i < 8; i++) {
        float4 st;
        st.x = acc[i][0] + bias.x;
        st.y = acc[i][1] + bias.y;
        st.z = acc[i][2] + bias.z;
        st.w = acc[i][3] + bias.w;
        *(float4*)&out[(size_t)(m0 + ty * 8 + i) * E_ + n0 + tx * 4] = st;
    }
}

// ---------------------------------------------------------------------------
extern "C" void kernel_launch(void* const* d_in, const int* in_sizes, int n_in,
                              void* d_out, int out_size)
{
    // metadata order: k, q, v, mask, Wk, Wq, Wv, Wp, bp
    const float* k  = (const float*)d_in[0];
    const float* q  = (const float*)d_in[1];
    const float* v  = (const float*)d_in[2];
    // d_in[3] = mask: unused — causality implemented directly
    const float* Wk = (const float*)d_in[4];
    const float* Wq = (const float*)d_in[5];
    const float* Wv = (const float*)d_in[6];
    const float* Wp = (const float*)d_in[7];
    const float* bp = (const float*)d_in[8];
    float* out = (float*)d_out;

    const int FLASH_SMEM = (64 * 64 + 64 * 65 + 64 * 64 + 64 * 68) * (int)sizeof(float);
    cudaFuncSetAttribute(flash_kernel,
                         cudaFuncAttributeMaxDynamicSharedMemorySize, FLASH_SMEM);

    dim3 gp(T_ / 128, B_ * H_, 3);
    proj_kernel<<<gp, 256>>>(q, k, v, Wq, Wk, Wv);

    dim3 gf(T_ / 64, B_ * H_);
    flash_kernel<<<gf, 256, FLASH_SMEM>>>();

    dim3 go((B_ * T_) / 128, E_ / 64);
    outproj_kernel<<<go, 256>>>(Wp, bp, out);
}

// round 3
// speedup vs baseline: 3.1967x; 3.1967x over previous
#include <cuda_runtime.h>
#include <math.h>
#include <stdint.h>

#define B_ 4
#define T_ 2048
#define E_ 1024
#define H_ 16

// Scratch (device globals: allocation-free).
// g_projF: [3][B][T][E], heads concatenated on last dim (n = h*64+d).
//   which 0 = xq (pre-scaled by 1/sqrt(E)), 1 = xk, 2 = xv.
// g_attn: flash output [B,T,E].  g_Wt: [3][E][E], row n = h*64+d, col e.
__device__ float g_projF[(size_t)3 * B_ * T_ * E_];
__device__ float g_attn[(size_t)B_ * T_ * E_];
__device__ float g_Wt[(size_t)3 * E_ * E_];

// ============================================================================
// mma.sync tf32 helpers (standard PTX, works at compute_103)
// ============================================================================
__device__ __forceinline__ uint32_t f2tf(float x) {
    uint32_t r;
    asm("cvt.rna.tf32.f32 %0, %1;" : "=r"(r) : "f"(x));
    return r;
}

// D(16x8) += A(16x8) * B(8x8); A row-major frag, B col-major frag, fp32 accum.
__device__ __forceinline__ void mma8(float* c, const uint32_t* a, const uint32_t* b) {
    asm volatile(
        "mma.sync.aligned.m16n8k8.row.col.f32.tf32.tf32.f32 "
        "{%0,%1,%2,%3}, {%4,%5,%6,%7}, {%8,%9}, {%0,%1,%2,%3};"
        : "+f"(c[0]), "+f"(c[1]), "+f"(c[2]), "+f"(c[3])
        : "r"(a[0]), "r"(a[1]), "r"(a[2]), "r"(a[3]), "r"(b[0]), "r"(b[1]));
}

// ============================================================================
// Weight transpose: g_Wt[which][h*64+d][e] = W[which][h][e][d]
// ============================================================================
__global__ __launch_bounds__(256) void transpose_w_kernel(
    const float* __restrict__ Wq, const float* __restrict__ Wk,
    const float* __restrict__ Wv)
{
    __shared__ float tile[64][65];
    const int which = blockIdx.z;
    const int h     = blockIdx.y;
    const int e0    = blockIdx.x * 64;
    const float* W = (which == 0 ? Wq : (which == 1 ? Wk : Wv)) + (size_t)h * E_ * 64;
    const int tid = threadIdx.x;

#pragma unroll
    for (int u = 0; u < 16; u++) {
        int idx = tid + u * 256;
        int r = idx >> 6, c = idx & 63;
        tile[r][c] = W[(size_t)(e0 + r) * 64 + c];
    }
    __syncthreads();

    float* out = g_Wt + (size_t)which * E_ * E_;
#pragma unroll
    for (int u = 0; u < 16; u++) {
        int idx = tid + u * 256;
        int d = idx >> 6, ee = idx & 63;
        out[(size_t)(h * 64 + d) * E_ + e0 + ee] = tile[ee][d];
    }
}

// ============================================================================
// GEMM core: C_tile[128,128] = A[128 rows, K=1024] @ B[128 rows, K=1024]^T
// Both operands K-major with row stride E_. 256 threads, 8 warps (4M x 2N),
// warp tile 32x64. BK=32. smem row stride 36 (frag LDS conflict-free).
// ============================================================================
#define LDT 36

__device__ __forceinline__ void gemm_tile(
    const float* __restrict__ A, const float* __restrict__ Bm,
    uint32_t* sA, uint32_t* sB, float C[2][8][4])
{
    const int tid = threadIdx.x, wid = tid >> 5, lane = tid & 31;
    const int g = lane >> 2, tg = lane & 3;
    const int mw = (wid & 3) * 32, nw = (wid >> 2) * 64;

#pragma unroll
    for (int i = 0; i < 2; i++)
#pragma unroll
        for (int j = 0; j < 8; j++)
#pragma unroll
            for (int p = 0; p < 4; p++) C[i][j][p] = 0.f;

    float4 ra[4], rb[4];

    // prologue: load k-chunk 0
#pragma unroll
    for (int u = 0; u < 4; u++) {
        int idx = tid + (u << 8);
        int r = idx >> 3, q = idx & 7;
        ra[u] = *(const float4*)(A + (size_t)r * E_ + (q << 2));
        rb[u] = *(const float4*)(Bm + (size_t)r * E_ + (q << 2));
    }
#pragma unroll
    for (int u = 0; u < 4; u++) {
        int idx = tid + (u << 8);
        int r = idx >> 3, q = idx & 7;
        uint4 ta, tb;
        ta.x = f2tf(ra[u].x); ta.y = f2tf(ra[u].y);
        ta.z = f2tf(ra[u].z); ta.w = f2tf(ra[u].w);
        tb.x = f2tf(rb[u].x); tb.y = f2tf(rb[u].y);
        tb.z = f2tf(rb[u].z); tb.w = f2tf(rb[u].w);
        *(uint4*)&sA[r * LDT + (q << 2)] = ta;
        *(uint4*)&sB[r * LDT + (q << 2)] = tb;
    }
    __syncthreads();

    for (int c = 0; c < 32; c++) {
        // prefetch next k-chunk into registers (latency hidden by compute)
        if (c < 31) {
            const int k0 = (c + 1) << 5;
#pragma unroll
            for (int u = 0; u < 4; u++) {
                int idx = tid + (u << 8);
                int r = idx >> 3, q = idx & 7;
                ra[u] = *(const float4*)(A + (size_t)r * E_ + k0 + (q << 2));
                rb[u] = *(const float4*)(Bm + (size_t)r * E_ + k0 + (q << 2));
            }
        }

        // compute 4 k-steps of 8
#pragma unroll
        for (int ks = 0; ks < 4; ks++) {
            uint32_t af[2][4], bf[8][2];
#pragma unroll
            for (int i = 0; i < 2; i++) {
                int base = (mw + 16 * i + g) * LDT + tg + 8 * ks;
                af[i][0] = sA[base];
                af[i][1] = sA[base + 8 * LDT];
                af[i][2] = sA[base + 4];
                af[i][3] = sA[base + 8 * LDT + 4];
            }
#pragma unroll
            for (int j = 0; j < 8; j++) {
                int base = (nw + 8 * j + g) * LDT + tg + 8 * ks;
                bf[j][0] = sB[base];
                bf[j][1] = sB[base + 4];
            }
#pragma unroll
            for (int i = 0; i < 2; i++)
#pragma unroll
                for (int j = 0; j < 8; j++) mma8(C[i][j], af[i], bf[j]);
        }
        __syncthreads();
        if (c < 31) {
#pragma unroll
            for (int u = 0; u < 4; u++) {
                int idx = tid + (u << 8);
                int r = idx >> 3, q = idx & 7;
                uint4 ta, tb;
                ta.x = f2tf(ra[u].x); ta.y = f2tf(ra[u].y);
                ta.z = f2tf(ra[u].z); ta.w = f2tf(ra[u].w);
                tb.x = f2tf(rb[u].x); tb.y = f2tf(rb[u].y);
                tb.z = f2tf(rb[u].z); tb.w = f2tf(rb[u].w);
                *(uint4*)&sA[r * LDT + (q << 2)] = ta;
                *(uint4*)&sB[r * LDT + (q << 2)] = tb;
            }
            __syncthreads();
        }
    }
}

// ============================================================================
// QKV projection: grid (T/128, E/128, 12 = which*4+b).  xq scaled by 1/32.
// ============================================================================
__global__ __launch_bounds__(256, 2) void proj_mma_kernel(
    const float* __restrict__ q, const float* __restrict__ k,
    const float* __restrict__ v)
{
    __shared__ uint32_t sA[128 * LDT];
    __shared__ uint32_t sB[128 * LDT];

    const int which = blockIdx.z >> 2;
    const int b     = blockIdx.z & 3;
    const int t0    = blockIdx.x * 128;
    const int n0    = blockIdx.y * 128;
    const float* X  = (which == 0 ? q : (which == 1 ? k : v)) +
                      (size_t)b * T_ * E_ + (size_t)t0 * E_;
    const float* Bm = g_Wt + (size_t)which * E_ * E_ + (size_t)n0 * E_;

    float C[2][8][4];
    gemm_tile(X, Bm, sA, sB, C);

    const float scale = (which == 0) ? 0.03125f : 1.0f;
    const int lane = threadIdx.x & 31, wid = threadIdx.x >> 5;
    const int g = lane >> 2, tg = lane & 3;
    const int mw = (wid & 3) * 32, nw = (wid >> 2) * 64;
    float* Cp = g_projF + ((size_t)which * B_ + b) * T_ * E_;

#pragma unroll
    for (int i = 0; i < 2; i++) {
        size_t r = (size_t)(t0 + mw + 16 * i + g);
#pragma unroll
        for (int j = 0; j < 8; j++) {
            int cc = n0 + nw + 8 * j + 2 * tg;
            float2 v0 = {C[i][j][0] * scale, C[i][j][1] * scale};
            float2 v1 = {C[i][j][2] * scale, C[i][j][3] * scale};
            *(float2*)&Cp[r * E_ + cc] = v0;
            *(float2*)&Cp[(r + 8) * E_ + cc] = v1;
        }
    }
}

// ============================================================================
// Output projection: out = g_attn[8192,1024] @ Wp^T + bp.
// grid (8192/128, 1024/128).
// ============================================================================
__global__ __launch_bounds__(256, 2) void outproj_mma_kernel(
    const float* __restrict__ Wp, const float* __restrict__ bp,
    float* __restrict__ out)
{
    __shared__ uint32_t sA[128 * LDT];
    __shared__ uint32_t sB[128 * LDT];

    const int m0 = blockIdx.x * 128;
    const int n0 = blockIdx.y * 128;

    float C[2][8][4];
    gemm_tile(g_attn + (size_t)m0 * E_, Wp + (size_t)n0 * E_, sA, sB, C);

    const int lane = threadIdx.x & 31, wid = threadIdx.x >> 5;
    const int g = lane >> 2, tg = lane & 3;
    const int mw = (wid & 3) * 32, nw = (wid >> 2) * 64;

#pragma unroll
    for (int i = 0; i < 2; i++) {
        size_t r = (size_t)(m0 + mw + 16 * i + g);
#pragma unroll
        for (int j = 0; j < 8; j++) {
            int cc = n0 + nw + 8 * j + 2 * tg;
            float2 bv = *(const float2*)&bp[cc];
            float2 v0 = {C[i][j][0] + bv.x, C[i][j][1] + bv.y};
            float2 v1 = {C[i][j][2] + bv.x, C[i][j][3] + bv.y};
            *(float2*)&out[r * E_ + cc] = v0;
            *(float2*)&out[(r + 8) * E_ + cc] = v1;
        }
    }
}

// ============================================================================
// Causal flash attention with mma.sync tf32.
// grid (T/64, B*H), 128 threads (4 warps), warp owns a 16-row strip.
// Q tile 64x64 (frags in regs), KV tiles 64x64 streamed. Online softmax on
// C-fragments. P routed through per-warp-private smem strips.
// ============================================================================
#define KLD 68   // Ks row stride (words): frag bank = 4g+tg, conflict-free
#define VLD 72   // Vs/Ps row stride: V-frag bank = 8tg+g, P-frag = 8g+tg, cf.

__global__ __launch_bounds__(128, 3) void flash_mma_kernel()
{
    extern __shared__ uint32_t smf[];
    uint32_t* Ks = smf;               // [64][KLD]
    uint32_t* Vs = Ks + 64 * KLD;     // [64][VLD]
    uint32_t* Ps = Vs + 64 * VLD;     // [64][VLD] (also Q staging)

    const int bh = blockIdx.y, b = bh >> 4, h = bh & 15;
    const int qt = gridDim.x - 1 - blockIdx.x;   // longest CTAs first
    const int tid = threadIdx.x, wid = tid >> 5, lane = tid & 31;
    const int g = lane >> 2, tg = lane & 3;

    const float* Q = g_projF + ((size_t)0 * B_ + b) * T_ * E_ +
                     (size_t)(qt * 64) * E_ + h * 64;
    const float* K = g_projF + ((size_t)1 * B_ + b) * T_ * E_ + h * 64;
    const float* V = g_projF + ((size_t)2 * B_ + b) * T_ * E_ + h * 64;

    // ---- stage Q -> Ps (raw fp32 bits), build tf32 A-fragments in regs ----
#pragma unroll
    for (int u = 0; u < 8; u++) {
        int idx = tid + u * 128;
        int r = idx >> 4, q4 = (idx & 15) << 2;
        *(float4*)&Ps[r * VLD + q4] = *(const float4*)&Q[(size_t)r * E_ + q4];
    }
    __syncthreads();

    uint32_t qf[8][4];
    {
        const float* Pf = (const float*)Ps;
        int rb = (wid * 16 + g) * VLD;
#pragma unroll
        for (int ks = 0; ks < 8; ks++) {
            qf[ks][0] = f2tf(Pf[rb + tg + 8 * ks]);
            qf[ks][1] = f2tf(Pf[rb + 8 * VLD + tg + 8 * ks]);
            qf[ks][2] = f2tf(Pf[rb + tg + 4 + 8 * ks]);
            qf[ks][3] = f2tf(Pf[rb + 8 * VLD + tg + 4 + 8 * ks]);
        }
    }

    float O[8][4];
#pragma unroll
    for (int j = 0; j < 8; j++)
#pragma unroll
        for (int p = 0; p < 4; p++) O[j][p] = 0.f;
    float m0 = -INFINITY, m1 = -INFINITY, l0 = 0.f, l1 = 0.f;

    for (int kt = 0; kt <= qt; kt++) {
        __syncthreads();   // prior tile's reads (incl. Q-frag build) complete
        // ---- load K,V tiles (cvt to tf32 at store) ----
#pragma unroll
        for (int u = 0; u < 8; u++) {
            int idx = tid + u * 128;
            int r = idx >> 4, q4 = (idx & 15) << 2;
            float4 kv = *(const float4*)&K[(size_t)(kt * 64 + r) * E_ + q4];
            float4 vv = *(const float4*)&V[(size_t)(kt * 64 + r) * E_ + q4];
            uint4 tk, tv;
            tk.x = f2tf(kv.x); tk.y = f2tf(kv.y); tk.z = f2tf(kv.z); tk.w = f2tf(kv.w);
            tv.x = f2tf(vv.x); tv.y = f2tf(vv.y); tv.z = f2tf(vv.z); tv.w = f2tf(vv.w);
            *(uint4*)&Ks[r * KLD + q4] = tk;
            *(uint4*)&Vs[r * VLD + q4] = tv;
        }
        __syncthreads();

        // ---- S = Q @ K^T ----
        float S[8][4];
#pragma unroll
        for (int j = 0; j < 8; j++)
#pragma unroll
            for (int p = 0; p < 4; p++) S[j][p] = 0.f;

#pragma unroll
        for (int ks = 0; ks < 8; ks++) {
            uint32_t bf[8][2];
#pragma unroll
            for (int j = 0; j < 8; j++) {
                int base = (g + 8 * j) * KLD + tg + 8 * ks;
                bf[j][0] = Ks[base];
                bf[j][1] = Ks[base + 4];
            }
#pragma unroll
            for (int j = 0; j < 8; j++) mma8(S[j], qf[ks], bf[j]);
        }

        // ---- causal mask on diagonal tile ----
        if (kt == qt) {
            int r0 = wid * 16 + g, r1 = r0 + 8;
#pragma unroll
            for (int j = 0; j < 8; j++) {
                int c0 = 8 * j + 2 * tg;
                if (c0 > r0) S[j][0] = -INFINITY;
                if (c0 + 1 > r0) S[j][1] = -INFINITY;
                if (c0 > r1) S[j][2] = -INFINITY;
                if (c0 + 1 > r1) S[j][3] = -INFINITY;
            }
        }

        // ---- online softmax (rows g and g+8; 4 lanes per row share cols) ----
        float rm0 = -INFINITY, rm1 = -INFINITY;
#pragma unroll
        for (int j = 0; j < 8; j++) {
            rm0 = fmaxf(rm0, fmaxf(S[j][0], S[j][1]));
            rm1 = fmaxf(rm1, fmaxf(S[j][2], S[j][3]));
        }
        rm0 = fmaxf(rm0, __shfl_xor_sync(0xffffffffu, rm0, 1));
        rm0 = fmaxf(rm0, __shfl_xor_sync(0xffffffffu, rm0, 2));
        rm1 = fmaxf(rm1, __shfl_xor_sync(0xffffffffu, rm1, 1));
        rm1 = fmaxf(rm1, __shfl_xor_sync(0xffffffffu, rm1, 2));

        float mn0 = fmaxf(m0, rm0), mn1 = fmaxf(m1, rm1);
        float a0 = __expf(m0 - mn0), a1 = __expf(m1 - mn1);
        float s0 = 0.f, s1 = 0.f;
#pragma unroll
        for (int j = 0; j < 8; j++) {
            S[j][0] = __expf(S[j][0] - mn0);
            S[j][1] = __expf(S[j][1] - mn0);
            S[j][2] = __expf(S[j][2] - mn1);
            S[j][3] = __expf(S[j][3] - mn1);
            s0 += S[j][0] + S[j][1];
            s1 += S[j][2] + S[j][3];
        }
        s0 += __shfl_xor_sync(0xffffffffu, s0, 1);
        s0 += __shfl_xor_sync(0xffffffffu, s0, 2);
        s1 += __shfl_xor_sync(0xffffffffu, s1, 1);
        s1 += __shfl_xor_sync(0xffffffffu, s1, 2);
        l0 = l0 * a0 + s0;
        l1 = l1 * a1 + s1;
        m0 = mn0;
        m1 = mn1;
#pragma unroll
        for (int j = 0; j < 8; j++) {
            O[j][0] *= a0; O[j][1] *= a0;
            O[j][2] *= a1; O[j][3] *= a1;
        }

        // ---- stage P into per-warp-private smem strip (cvt to tf32) ----
        {
            int pr0 = (wid * 16 + g) * VLD, pr1 = pr0 + 8 * VLD;
#pragma unroll
            for (int j = 0; j < 8; j++) {
                int cc = 8 * j + 2 * tg;
                uint2 p0 = {f2tf(S[j][0]), f2tf(S[j][1])};
                uint2 p1 = {f2tf(S[j][2]), f2tf(S[j][3])};
                *(uint2*)&Ps[pr0 + cc] = p0;
                *(uint2*)&Ps[pr1 + cc] = p1;
            }
        }
        __syncwarp();

        // ---- O += P @ V ----
#pragma unroll
        for (int ks = 0; ks < 8; ks++) {
            uint32_t af[4], bf[8][2];
            int base = (wid * 16 + g) * VLD + tg + 8 * ks;
            af[0] = Ps[base];
            af[1] = Ps[base + 8 * VLD];
            af[2] = Ps[base + 4];
            af[3] = Ps[base + 8 * VLD + 4];
#pragma unroll
            for (int j = 0; j < 8; j++) {
                int vb = (8 * ks + tg) * VLD + g + 8 * j;
                bf[j][0] = Vs[vb];
                bf[j][1] = Vs[vb + 4 * VLD];
            }
#pragma unroll
            for (int j = 0; j < 8; j++) mma8(O[j], af, bf[j]);
        }
    }

    // ---- epilogue: normalize, write concatenated-head layout ----
    float inv0 = 1.f / l0, inv1 = 1.f / l1;
    float* outp = g_attn + ((size_t)b * T_ + (size_t)qt * 64 + wid * 16 + g) * E_ + h * 64;
#pragma unroll
    for (int j = 0; j < 8; j++) {
        int cc = 8 * j + 2 * tg;
        float2 v0 = {O[j][0] * inv0, O[j][1] * inv0};
        float2 v1 = {O[j][2] * inv1, O[j][3] * inv1};
        *(float2*)&outp[cc] = v0;
        *(float2*)(outp + 8 * E_ + cc) = v1;
    }
}

// ============================================================================
extern "C" void kernel_launch(void* const* d_in, const int* in_sizes, int n_in,
                              void* d_out, int out_size)
{
    // metadata order: k, q, v, mask, Wk, Wq, Wv, Wp, bp
    const float* k  = (const float*)d_in[0];
    const float* q  = (const float*)d_in[1];
    const float* v  = (const float*)d_in[2];
    const float* Wk = (const float*)d_in[4];
    const float* Wq = (const float*)d_in[5];
    const float* Wv = (const float*)d_in[6];
    const float* Wp = (const float*)d_in[7];
    const float* bp = (const float*)d_in[8];
    float* out = (float*)d_out;

    const int FLASH_SMEM = (64 * KLD + 64 * VLD + 64 * VLD) * (int)sizeof(uint32_t);
    cudaFuncSetAttribute(flash_mma_kernel,
                         cudaFuncAttributeMaxDynamicSharedMemorySize, FLASH_SMEM);

    transpose_w_kernel<<<dim3(E_ / 64, H_, 3), 256>>>(Wq, Wk, Wv);

    proj_mma_kernel<<<dim3(T_ / 128, E_ / 128, 12), 256>>>(q, k, v);

    flash_mma_kernel<<<dim3(T_ / 64, B_ * H_), 128, FLASH_SMEM>>>();

    outproj_mma_kernel<<<dim3((B_ * T_) / 128, E_ / 128), 256>>>(Wp, bp, out);
}

// round 4
// speedup vs baseline: 3.3302x; 1.0418x over previous
#include <cuda_runtime.h>
#include <math.h>
#include <stdint.h>

#define B_ 4
#define T_ 2048
#define E_ 1024
#define H_ 16

// Device-global scratch (allocation-free).
// g_X:     [3][B*T*E]  tf32-rounded copies of q,k,v inputs
// g_Wp:    [E*E]       tf32-rounded Wp
// g_Wt:    [3][E*E]    tf32-rounded transposed per-head weights (row n=h*64+d)
// g_projF: [3][B][T][E] xq(,*1/32)/xk/xv, tf32-rounded values, heads concat
// g_attn:  [B][T][E]   flash output, tf32-rounded values
__device__ float g_X[(size_t)3 * B_ * T_ * E_];
__device__ float g_Wp[(size_t)E_ * E_];
__device__ float g_Wt[(size_t)3 * E_ * E_];
__device__ float g_projF[(size_t)3 * B_ * T_ * E_];
__device__ float g_attn[(size_t)B_ * T_ * E_];

// ============================================================================
// Helpers
// ============================================================================
__device__ __forceinline__ uint32_t f2tf(float x) {
    uint32_t r;
    asm("cvt.rna.tf32.f32 %0, %1;" : "=r"(r) : "f"(x));
    return r;
}
__device__ __forceinline__ float rnd_tf(float x) { return __uint_as_float(f2tf(x)); }

__device__ __forceinline__ uint32_t smem_u32(const void* p) {
    uint32_t a;
    asm("{ .reg .u64 t; cvta.to.shared.u64 t, %1; cvt.u32.u64 %0, t; }"
        : "=r"(a) : "l"(p));
    return a;
}

__device__ __forceinline__ void mma8(float* c, const uint32_t* a, const uint32_t* b) {
    asm volatile(
        "mma.sync.aligned.m16n8k8.row.col.f32.tf32.tf32.f32 "
        "{%0,%1,%2,%3}, {%4,%5,%6,%7}, {%8,%9}, {%0,%1,%2,%3};"
        : "+f"(c[0]), "+f"(c[1]), "+f"(c[2]), "+f"(c[3])
        : "r"(a[0]), "r"(a[1]), "r"(a[2]), "r"(a[3]), "r"(b[0]), "r"(b[1]));
}

__device__ __forceinline__ void cp16(uint32_t dst, const void* src) {
    asm volatile("cp.async.cg.shared.global [%0], [%1], 16;"
                 :: "r"(dst), "l"(src));
}
#define CP_COMMIT asm volatile("cp.async.commit_group;" ::: "memory")
#define CP_WAIT0  asm volatile("cp.async.wait_group 0;" ::: "memory")
#define CP_WAIT1  asm volatile("cp.async.wait_group 1;" ::: "memory")

// ============================================================================
// Round pass: g_X[z] = rna_tf32(q|k|v), g_Wp = rna_tf32(Wp)
// grid (8192, 4), 256 threads, float4 per thread.
// ============================================================================
__global__ __launch_bounds__(256) void cvt_round_kernel(
    const float* __restrict__ q, const float* __restrict__ k,
    const float* __restrict__ v, const float* __restrict__ Wp)
{
    const int z = blockIdx.y;
    const float* src;
    float* dst;
    size_t n4;
    if (z < 3) {
        src = (z == 0 ? q : (z == 1 ? k : v));
        dst = g_X + (size_t)z * B_ * T_ * E_;
        n4  = (size_t)B_ * T_ * E_ / 4;
    } else {
        src = Wp;
        dst = g_Wp;
        n4  = (size_t)E_ * E_ / 4;
    }
    size_t i = (size_t)blockIdx.x * 256 + threadIdx.x;
    if (i < n4) {
        float4 x = ((const float4*)src)[i];
        float4 o;
        o.x = rnd_tf(x.x); o.y = rnd_tf(x.y);
        o.z = rnd_tf(x.z); o.w = rnd_tf(x.w);
        ((float4*)dst)[i] = o;
    }
}

// ============================================================================
// Weight transpose + round: g_Wt[which][h*64+d][e] = rna(W[which][h][e][d])
// ============================================================================
__global__ __launch_bounds__(256) void transpose_w_kernel(
    const float* __restrict__ Wq, const float* __restrict__ Wk,
    const float* __restrict__ Wv)
{
    __shared__ float tile[64][65];
    const int which = blockIdx.z;
    const int h     = blockIdx.y;
    const int e0    = blockIdx.x * 64;
    const float* W = (which == 0 ? Wq : (which == 1 ? Wk : Wv)) + (size_t)h * E_ * 64;
    const int tid = threadIdx.x;

#pragma unroll
    for (int u = 0; u < 16; u++) {
        int idx = tid + u * 256;
        int r = idx >> 6, c = idx & 63;
        tile[r][c] = W[(size_t)(e0 + r) * 64 + c];
    }
    __syncthreads();

    float* out = g_Wt + (size_t)which * E_ * E_;
#pragma unroll
    for (int u = 0; u < 16; u++) {
        int idx = tid + u * 256;
        int d = idx >> 6, ee = idx & 63;
        out[(size_t)(h * 64 + d) * E_ + e0 + ee] = rnd_tf(tile[ee][d]);
    }
}

// ============================================================================
// GEMM core (cp.async 3-stage): C[128,128] = A[128,K=1024] @ B[128,K=1024]^T
// Operands K-major, row stride E_, values pre-rounded to tf32.
// 256 threads / 8 warps (4M x 2N), warp tile 32x64, BK=32, smem stride 36.
// One __syncthreads per K-chunk.
// ============================================================================
#define LDT 36
#define GS_STAGE (128 * LDT)                    // words per operand-stage
#define GEMM_SMEM_BYTES (6 * GS_STAGE * 4)      // 110592

__device__ __forceinline__ void gemm_issue(
    const float* __restrict__ A, const float* __restrict__ Bm,
    uint32_t su, int c, int s, int tid)
{
    const float* Ac = A + (c << 5);
    const float* Bc = Bm + (c << 5);
    const uint32_t ab = su + (uint32_t)s * GS_STAGE * 4;
    const uint32_t bb = su + (uint32_t)(3 + s) * GS_STAGE * 4;
#pragma unroll
    for (int u = 0; u < 4; u++) {
        int idx = tid + (u << 8);
        int r = idx >> 3, qq = idx & 7;
        uint32_t so = (uint32_t)(r * LDT + (qq << 2)) * 4;
        cp16(ab + so, Ac + (size_t)r * E_ + (qq << 2));
        cp16(bb + so, Bc + (size_t)r * E_ + (qq << 2));
    }
    CP_COMMIT;
}

__device__ __forceinline__ void gemm_tile_async(
    const float* __restrict__ A, const float* __restrict__ Bm,
    uint32_t* smw, float C[2][8][4])
{
    const int tid = threadIdx.x, wid = tid >> 5, lane = tid & 31;
    const int g = lane >> 2, tg = lane & 3;
    const int mw = (wid & 3) * 32, nw = (wid >> 2) * 64;
    const uint32_t su = smem_u32(smw);

#pragma unroll
    for (int i = 0; i < 2; i++)
#pragma unroll
        for (int j = 0; j < 8; j++)
#pragma unroll
            for (int p = 0; p < 4; p++) C[i][j][p] = 0.f;

    gemm_issue(A, Bm, su, 0, 0, tid);
    gemm_issue(A, Bm, su, 1, 1, tid);

    int s = 0;                 // stage of chunk c
    for (int c = 0; c < 32; c++) {
        if (c < 31) { CP_WAIT1; } else { CP_WAIT0; }
        __syncthreads();
        if (c + 2 < 32) {
            int sn = s + 2; if (sn >= 3) sn -= 3;
            gemm_issue(A, Bm, su, c + 2, sn, tid);
        }
        const uint32_t* sA = smw + (size_t)s * GS_STAGE;
        const uint32_t* sB = smw + (size_t)(3 + s) * GS_STAGE;
#pragma unroll
        for (int ks = 0; ks < 4; ks++) {
            uint32_t af[2][4], bf[8][2];
#pragma unroll
            for (int i = 0; i < 2; i++) {
                int base = (mw + 16 * i + g) * LDT + tg + 8 * ks;
                af[i][0] = sA[base];
                af[i][1] = sA[base + 8 * LDT];
                af[i][2] = sA[base + 4];
                af[i][3] = sA[base + 8 * LDT + 4];
            }
#pragma unroll
            for (int j = 0; j < 8; j++) {
                int base = (nw + 8 * j + g) * LDT + tg + 8 * ks;
                bf[j][0] = sB[base];
                bf[j][1] = sB[base + 4];
            }
#pragma unroll
            for (int i = 0; i < 2; i++)
#pragma unroll
                for (int j = 0; j < 8; j++) mma8(C[i][j], af[i], bf[j]);
        }
        if (++s == 3) s = 0;
    }
}

// ============================================================================
// QKV projection: grid (T/128, E/128, 12 = which*4+b). xq scaled by 1/32.
// Epilogue rounds outputs to tf32 values (flash consumes raw bits).
// ============================================================================
__global__ __launch_bounds__(256, 2) void proj_mma_kernel()
{
    extern __shared__ uint32_t gsm[];
    const int which = blockIdx.z >> 2;
    const int b     = blockIdx.z & 3;
    const int t0    = blockIdx.x * 128;
    const int n0    = blockIdx.y * 128;
    const float* X  = g_X + ((size_t)which * B_ + b) * T_ * E_ + (size_t)t0 * E_;
    const float* Bm = g_Wt + (size_t)which * E_ * E_ + (size_t)n0 * E_;

    float C[2][8][4];
    gemm_tile_async(X, Bm, gsm, C);

    const float scale = (which == 0) ? 0.03125f : 1.0f;
    const int lane = threadIdx.x & 31, wid = threadIdx.x >> 5;
    const int g = lane >> 2, tg = lane & 3;
    const int mw = (wid & 3) * 32, nw = (wid >> 2) * 64;
    float* Cp = g_projF + ((size_t)which * B_ + b) * T_ * E_;

#pragma unroll
    for (int i = 0; i < 2; i++) {
        size_t r = (size_t)(t0 + mw + 16 * i + g);
#pragma unroll
        for (int j = 0; j < 8; j++) {
            int cc = n0 + nw + 8 * j + 2 * tg;
            float2 v0 = {rnd_tf(C[i][j][0] * scale), rnd_tf(C[i][j][1] * scale)};
            float2 v1 = {rnd_tf(C[i][j][2] * scale), rnd_tf(C[i][j][3] * scale)};
            *(float2*)&Cp[r * E_ + cc] = v0;
            *(float2*)&Cp[(r + 8) * E_ + cc] = v1;
        }
    }
}

// ============================================================================
// Output projection: out = g_attn[8192,1024] @ g_Wp^T + bp (fp32 epilogue).
// ============================================================================
__global__ __launch_bounds__(256, 2) void outproj_mma_kernel(
    const float* __restrict__ bp, float* __restrict__ out)
{
    extern __shared__ uint32_t gsm[];
    const int m0 = blockIdx.x * 128;
    const int n0 = blockIdx.y * 128;

    float C[2][8][4];
    gemm_tile_async(g_attn + (size_t)m0 * E_, g_Wp + (size_t)n0 * E_, gsm, C);

    const int lane = threadIdx.x & 31, wid = threadIdx.x >> 5;
    const int g = lane >> 2, tg = lane & 3;
    const int mw = (wid & 3) * 32, nw = (wid >> 2) * 64;

#pragma unroll
    for (int i = 0; i < 2; i++) {
        size_t r = (size_t)(m0 + mw + 16 * i + g);
#pragma unroll
        for (int j = 0; j < 8; j++) {
            int cc = n0 + nw + 8 * j + 2 * tg;
            float2 bv = *(const float2*)&bp[cc];
            float2 v0 = {C[i][j][0] + bv.x, C[i][j][1] + bv.y};
            float2 v1 = {C[i][j][2] + bv.x, C[i][j][3] + bv.y};
            *(float2*)&out[r * E_ + cc] = v0;
            *(float2*)&out[(r + 8) * E_ + cc] = v1;
        }
    }
}

// ============================================================================
// Causal flash attention, tf32 mma + cp.async double-buffered K/V.
// grid (T/64, B*H), 128 threads (4 warps). One barrier per kt iteration.
// ============================================================================
#define KLD 68
#define VLD 72
#define KS_W (64 * KLD)     // 4352 words per K stage
#define VS_W (64 * VLD)     // 4608 words per V stage
#define FLASH_SMEM_BYTES ((2 * KS_W + 2 * VS_W + VS_W) * 4)   // 90112

__global__ __launch_bounds__(128, 2) void flash_mma_kernel()
{
    extern __shared__ uint32_t smf[];
    uint32_t* Ks2 = smf;                        // [2][64][KLD]
    uint32_t* Vs2 = smf + 2 * KS_W;             // [2][64][VLD]
    uint32_t* Ps  = smf + 2 * KS_W + 2 * VS_W;  // [64][VLD] (also Q staging)

    const int bh = blockIdx.y, b = bh >> 4, h = bh & 15;
    const int qt = gridDim.x - 1 - blockIdx.x;   // longest CTAs first
    const int tid = threadIdx.x, wid = tid >> 5, lane = tid & 31;
    const int g = lane >> 2, tg = lane & 3;

    const float* Q = g_projF + ((size_t)0 * B_ + b) * T_ * E_ +
                     (size_t)(qt * 64) * E_ + h * 64;
    const float* K = g_projF + ((size_t)1 * B_ + b) * T_ * E_ + h * 64;
    const float* V = g_projF + ((size_t)2 * B_ + b) * T_ * E_ + h * 64;

    const uint32_t ks_u = smem_u32(Ks2);
    const uint32_t vs_u = smem_u32(Vs2);

    // issue K/V tile kt into stage s (cp.async, raw pre-rounded bits)
    auto issue_kv = [&](int kt, int s) {
        const uint32_t kb = ks_u + (uint32_t)s * KS_W * 4;
        const uint32_t vb = vs_u + (uint32_t)s * VS_W * 4;
#pragma unroll
        for (int u = 0; u < 8; u++) {
            int idx = tid + (u << 7);
            int r = idx >> 4, q4 = (idx & 15) << 2;
            size_t go = (size_t)(kt * 64 + r) * E_ + q4;
            cp16(kb + (uint32_t)(r * KLD + q4) * 4, K + go);
            cp16(vb + (uint32_t)(r * VLD + q4) * 4, V + go);
        }
        CP_COMMIT;
    };

    issue_kv(0, 0);

    // stage Q -> Ps (raw bits, already tf32-exact), build A-fragments
#pragma unroll
    for (int u = 0; u < 8; u++) {
        int idx = tid + (u << 7);
        int r = idx >> 4, q4 = (idx & 15) << 2;
        *(float4*)&Ps[r * VLD + q4] = *(const float4*)&Q[(size_t)r * E_ + q4];
    }
    __syncthreads();

    uint32_t qf[8][4];
    {
        int rb = (wid * 16 + g) * VLD;
#pragma unroll
        for (int ks = 0; ks < 8; ks++) {
            qf[ks][0] = Ps[rb + tg + 8 * ks];
            qf[ks][1] = Ps[rb + 8 * VLD + tg + 8 * ks];
            qf[ks][2] = Ps[rb + tg + 4 + 8 * ks];
            qf[ks][3] = Ps[rb + 8 * VLD + tg + 4 + 8 * ks];
        }
    }

    float O[8][4];
#pragma unroll
    for (int j = 0; j < 8; j++)
#pragma unroll
        for (int p = 0; p < 4; p++) O[j][p] = 0.f;
    float m0 = -INFINITY, m1 = -INFINITY, l0 = 0.f, l1 = 0.f;

    for (int kt = 0; kt <= qt; kt++) {
        CP_WAIT0;
        __syncthreads();   // KV(kt) visible; all warps done with kt-1 compute
        if (kt < qt) issue_kv(kt + 1, (kt + 1) & 1);

        const uint32_t* Ks = Ks2 + (size_t)(kt & 1) * KS_W;
        const uint32_t* Vs = Vs2 + (size_t)(kt & 1) * VS_W;

        // ---- S = Q @ K^T ----
        float S[8][4];
#pragma unroll
        for (int j = 0; j < 8; j++)
#pragma unroll
            for (int p = 0; p < 4; p++) S[j][p] = 0.f;

#pragma unroll
        for (int ks = 0; ks < 8; ks++) {
            uint32_t bf[8][2];
#pragma unroll
            for (int j = 0; j < 8; j++) {
                int base = (g + 8 * j) * KLD + tg + 8 * ks;
                bf[j][0] = Ks[base];
                bf[j][1] = Ks[base + 4];
            }
#pragma unroll
            for (int j = 0; j < 8; j++) mma8(S[j], qf[ks], bf[j]);
        }

        // ---- causal mask on diagonal tile ----
        if (kt == qt) {
            int r0 = wid * 16 + g, r1 = r0 + 8;
#pragma unroll
            for (int j = 0; j < 8; j++) {
                int c0 = 8 * j + 2 * tg;
                if (c0 > r0) S[j][0] = -INFINITY;
                if (c0 + 1 > r0) S[j][1] = -INFINITY;
                if (c0 > r1) S[j][2] = -INFINITY;
                if (c0 + 1 > r1) S[j][3] = -INFINITY;
            }
        }

        // ---- online softmax ----
        float rm0 = -INFINITY, rm1 = -INFINITY;
#pragma unroll
        for (int j = 0; j < 8; j++) {
            rm0 = fmaxf(rm0, fmaxf(S[j][0], S[j][1]));
            rm1 = fmaxf(rm1, fmaxf(S[j][2], S[j][3]));
        }
        rm0 = fmaxf(rm0, __shfl_xor_sync(0xffffffffu, rm0, 1));
        rm0 = fmaxf(rm0, __shfl_xor_sync(0xffffffffu, rm0, 2));
        rm1 = fmaxf(rm1, __shfl_xor_sync(0xffffffffu, rm1, 1));
        rm1 = fmaxf(rm1, __shfl_xor_sync(0xffffffffu, rm1, 2));

        float mn0 = fmaxf(m0, rm0), mn1 = fmaxf(m1, rm1);
        float a0 = __expf(m0 - mn0), a1 = __expf(m1 - mn1);
        float s0 = 0.f, s1 = 0.f;
#pragma unroll
        for (int j = 0; j < 8; j++) {
            S[j][0] = __expf(S[j][0] - mn0);
            S[j][1] = __expf(S[j][1] - mn0);
            S[j][2] = __expf(S[j][2] - mn1);
            S[j][3] = __expf(S[j][3] - mn1);
            s0 += S[j][0] + S[j][1];
            s1 += S[j][2] + S[j][3];
        }
        s0 += __shfl_xor_sync(0xffffffffu, s0, 1);
        s0 += __shfl_xor_sync(0xffffffffu, s0, 2);
        s1 += __shfl_xor_sync(0xffffffffu, s1, 1);
        s1 += __shfl_xor_sync(0xffffffffu, s1, 2);
        l0 = l0 * a0 + s0;
        l1 = l1 * a1 + s1;
        m0 = mn0;
        m1 = mn1;
#pragma unroll
        for (int j = 0; j < 8; j++) {
            O[j][0] *= a0; O[j][1] *= a0;
            O[j][2] *= a1; O[j][3] *= a1;
        }

        // ---- stage P into per-warp-private smem strip (round to tf32) ----
        {
            int pr0 = (wid * 16 + g) * VLD, pr1 = pr0 + 8 * VLD;
#pragma unroll
            for (int j = 0; j < 8; j++) {
                int cc = 8 * j + 2 * tg;
                uint2 p0 = {f2tf(S[j][0]), f2tf(S[j][1])};
                uint2 p1 = {f2tf(S[j][2]), f2tf(S[j][3])};
                *(uint2*)&Ps[pr0 + cc] = p0;
                *(uint2*)&Ps[pr1 + cc] = p1;
            }
        }
        __syncwarp();

        // ---- O += P @ V ----
#pragma unroll
        for (int ks = 0; ks < 8; ks++) {
            uint32_t af[4], bf[8][2];
            int base = (wid * 16 + g) * VLD + tg + 8 * ks;
            af[0] = Ps[base];
            af[1] = Ps[base + 8 * VLD];
            af[2] = Ps[base + 4];
            af[3] = Ps[base + 8 * VLD + 4];
#pragma unroll
            for (int j = 0; j < 8; j++) {
                int vb = (8 * ks + tg) * VLD + g + 8 * j;
                bf[j][0] = Vs[vb];
                bf[j][1] = Vs[vb + 4 * VLD];
            }
#pragma unroll
            for (int j = 0; j < 8; j++) mma8(O[j], af, bf[j]);
        }
    }

    // ---- epilogue: normalize, round to tf32, write [B,T,E] ----
    float inv0 = 1.f / l0, inv1 = 1.f / l1;
    float* outp = g_attn + ((size_t)b * T_ + (size_t)qt * 64 + wid * 16 + g) * E_ + h * 64;
#pragma unroll
    for (int j = 0; j < 8; j++) {
        int cc = 8 * j + 2 * tg;
        float2 v0 = {rnd_tf(O[j][0] * inv0), rnd_tf(O[j][1] * inv0)};
        float2 v1 = {rnd_tf(O[j][2] * inv1), rnd_tf(O[j][3] * inv1)};
        *(float2*)&outp[cc] = v0;
        *(float2*)(outp + 8 * E_ + cc) = v1;
    }
}

// ============================================================================
extern "C" void kernel_launch(void* const* d_in, const int* in_sizes, int n_in,
                              void* d_out, int out_size)
{
    // metadata order: k, q, v, mask, Wk, Wq, Wv, Wp, bp
    const float* k  = (const float*)d_in[0];
    const float* q  = (const float*)d_in[1];
    const float* v  = (const float*)d_in[2];
    const float* Wk = (const float*)d_in[4];
    const float* Wq = (const float*)d_in[5];
    const float* Wv = (const float*)d_in[6];
    const float* Wp = (const float*)d_in[7];
    const float* bp = (const float*)d_in[8];
    float* out = (float*)d_out;

    cudaFuncSetAttribute(proj_mma_kernel,
                         cudaFuncAttributeMaxDynamicSharedMemorySize, GEMM_SMEM_BYTES);
    cudaFuncSetAttribute(outproj_mma_kernel,
                         cudaFuncAttributeMaxDynamicSharedMemorySize, GEMM_SMEM_BYTES);
    cudaFuncSetAttribute(flash_mma_kernel,
                         cudaFuncAttributeMaxDynamicSharedMemorySize, FLASH_SMEM_BYTES);

    cvt_round_kernel<<<dim3(8192, 4), 256>>>(q, k, v, Wp);

    transpose_w_kernel<<<dim3(E_ / 64, H_, 3), 256>>>(Wq, Wk, Wv);

    proj_mma_kernel<<<dim3(T_ / 128, E_ / 128, 12), 256, GEMM_SMEM_BYTES>>>();

    flash_mma_kernel<<<dim3(T_ / 64, B_ * H_), 128, FLASH_SMEM_BYTES>>>();

    outproj_mma_kernel<<<dim3((B_ * T_) / 128, E_ / 128), 256, GEMM_SMEM_BYTES>>>(bp, out);
}

// round 5
// speedup vs baseline: 3.3617x; 1.0094x over previous
#include <cuda_runtime.h>
#include <math.h>
#include <stdint.h>

#define B_ 4
#define T_ 2048
#define E_ 1024
#define H_ 16

// Device-global scratch (allocation-free).
__device__ float g_X[(size_t)3 * B_ * T_ * E_];
__device__ float g_Wp[(size_t)E_ * E_];
__device__ float g_Wt[(size_t)3 * E_ * E_];
__device__ float g_projF[(size_t)3 * B_ * T_ * E_];
__device__ float g_attn[(size_t)B_ * T_ * E_];

// ============================================================================
// Helpers
// ============================================================================
__device__ __forceinline__ uint32_t f2tf(float x) {
    uint32_t r;
    asm("cvt.rna.tf32.f32 %0, %1;" : "=r"(r) : "f"(x));
    return r;
}
__device__ __forceinline__ float rnd_tf(float x) { return __uint_as_float(f2tf(x)); }

__device__ __forceinline__ uint32_t smem_u32(const void* p) {
    uint32_t a;
    asm("{ .reg .u64 t; cvta.to.shared.u64 t, %1; cvt.u32.u64 %0, t; }"
        : "=r"(a) : "l"(p));
    return a;
}

__device__ __forceinline__ void mma8(float* c, const uint32_t* a, const uint32_t* b) {
    asm volatile(
        "mma.sync.aligned.m16n8k8.row.col.f32.tf32.tf32.f32 "
        "{%0,%1,%2,%3}, {%4,%5,%6,%7}, {%8,%9}, {%0,%1,%2,%3};"
        : "+f"(c[0]), "+f"(c[1]), "+f"(c[2]), "+f"(c[3])
        : "r"(a[0]), "r"(a[1]), "r"(a[2]), "r"(a[3]), "r"(b[0]), "r"(b[1]));
}

__device__ __forceinline__ void cp16(uint32_t dst, const void* src) {
    asm volatile("cp.async.cg.shared.global [%0], [%1], 16;"
                 :: "r"(dst), "l"(src));
}
#define CP_COMMIT asm volatile("cp.async.commit_group;" ::: "memory")
#define CP_WAIT0  asm volatile("cp.async.wait_group 0;" ::: "memory")
#define CP_WAIT1  asm volatile("cp.async.wait_group 1;" ::: "memory")

// ============================================================================
// Round pass: g_X[z] = rna_tf32(q|k|v), g_Wp = rna_tf32(Wp)
// ============================================================================
__global__ __launch_bounds__(256) void cvt_round_kernel(
    const float* __restrict__ q, const float* __restrict__ k,
    const float* __restrict__ v, const float* __restrict__ Wp)
{
    const int z = blockIdx.y;
    const float* src;
    float* dst;
    size_t n4;
    if (z < 3) {
        src = (z == 0 ? q : (z == 1 ? k : v));
        dst = g_X + (size_t)z * B_ * T_ * E_;
        n4  = (size_t)B_ * T_ * E_ / 4;
    } else {
        src = Wp;
        dst = g_Wp;
        n4  = (size_t)E_ * E_ / 4;
    }
    size_t i = (size_t)blockIdx.x * 256 + threadIdx.x;
    if (i < n4) {
        float4 x = ((const float4*)src)[i];
        float4 o;
        o.x = rnd_tf(x.x); o.y = rnd_tf(x.y);
        o.z = rnd_tf(x.z); o.w = rnd_tf(x.w);
        ((float4*)dst)[i] = o;
    }
}

// ============================================================================
// Weight transpose + round: g_Wt[which][h*64+d][e] = rna(W[which][h][e][d])
// ============================================================================
__global__ __launch_bounds__(256) void transpose_w_kernel(
    const float* __restrict__ Wq, const float* __restrict__ Wk,
    const float* __restrict__ Wv)
{
    __shared__ float tile[64][65];
    const int which = blockIdx.z;
    const int h     = blockIdx.y;
    const int e0    = blockIdx.x * 64;
    const float* W = (which == 0 ? Wq : (which == 1 ? Wk : Wv)) + (size_t)h * E_ * 64;
    const int tid = threadIdx.x;

#pragma unroll
    for (int u = 0; u < 16; u++) {
        int idx = tid + u * 256;
        int r = idx >> 6, c = idx & 63;
        tile[r][c] = W[(size_t)(e0 + r) * 64 + c];
    }
    __syncthreads();

    float* out = g_Wt + (size_t)which * E_ * E_;
#pragma unroll
    for (int u = 0; u < 16; u++) {
        int idx = tid + u * 256;
        int d = idx >> 6, ee = idx & 63;
        out[(size_t)(h * 64 + d) * E_ + e0 + ee] = rnd_tf(tile[ee][d]);
    }
}

// ============================================================================
// GEMM core (cp.async 3-stage): C[128,128] = A[128,K=1024] @ B[128,K=1024]^T
// 256 threads / 8 warps (4M x 2N), warp tile 32x64, BK=32, smem stride 36.
// ============================================================================
#define LDT 36
#define GS_STAGE (128 * LDT)
#define GEMM_SMEM_BYTES (6 * GS_STAGE * 4)

__device__ __forceinline__ void gemm_issue(
    const float* __restrict__ A, const float* __restrict__ Bm,
    uint32_t su, int c, int s, int tid)
{
    const float* Ac = A + (c << 5);
    const float* Bc = Bm + (c << 5);
    const uint32_t ab = su + (uint32_t)s * GS_STAGE * 4;
    const uint32_t bb = su + (uint32_t)(3 + s) * GS_STAGE * 4;
#pragma unroll
    for (int u = 0; u < 4; u++) {
        int idx = tid + (u << 8);
        int r = idx >> 3, qq = idx & 7;
        uint32_t so = (uint32_t)(r * LDT + (qq << 2)) * 4;
        cp16(ab + so, Ac + (size_t)r * E_ + (qq << 2));
        cp16(bb + so, Bc + (size_t)r * E_ + (qq << 2));
    }
    CP_COMMIT;
}

__device__ __forceinline__ void gemm_tile_async(
    const float* __restrict__ A, const float* __restrict__ Bm,
    uint32_t* smw, float C[2][8][4])
{
    const int tid = threadIdx.x, wid = tid >> 5, lane = tid & 31;
    const int g = lane >> 2, tg = lane & 3;
    const int mw = (wid & 3) * 32, nw = (wid >> 2) * 64;
    const uint32_t su = smem_u32(smw);

#pragma unroll
    for (int i = 0; i < 2; i++)
#pragma unroll
        for (int j = 0; j < 8; j++)
#pragma unroll
            for (int p = 0; p < 4; p++) C[i][j][p] = 0.f;

    gemm_issue(A, Bm, su, 0, 0, tid);
    gemm_issue(A, Bm, su, 1, 1, tid);

    int s = 0;
    for (int c = 0; c < 32; c++) {
        if (c < 31) { CP_WAIT1; } else { CP_WAIT0; }
        __syncthreads();
        if (c + 2 < 32) {
            int sn = s + 2; if (sn >= 3) sn -= 3;
            gemm_issue(A, Bm, su, c + 2, sn, tid);
        }
        const uint32_t* sA = smw + (size_t)s * GS_STAGE;
        const uint32_t* sB = smw + (size_t)(3 + s) * GS_STAGE;
#pragma unroll
        for (int ks = 0; ks < 4; ks++) {
            uint32_t af[2][4], bf[8][2];
#pragma unroll
            for (int i = 0; i < 2; i++) {
                int base = (mw + 16 * i + g) * LDT + tg + 8 * ks;
                af[i][0] = sA[base];
                af[i][1] = sA[base + 8 * LDT];
                af[i][2] = sA[base + 4];
                af[i][3] = sA[base + 8 * LDT + 4];
            }
#pragma unroll
            for (int j = 0; j < 8; j++) {
                int base = (nw + 8 * j + g) * LDT + tg + 8 * ks;
                bf[j][0] = sB[base];
                bf[j][1] = sB[base + 4];
            }
#pragma unroll
            for (int i = 0; i < 2; i++)
#pragma unroll
                for (int j = 0; j < 8; j++) mma8(C[i][j], af[i], bf[j]);
        }
        if (++s == 3) s = 0;
    }
}

// ============================================================================
// QKV projection: grid (T/128, E/128, 12). xq scaled by 1/32, tf32-rounded out.
// ============================================================================
__global__ __launch_bounds__(256, 2) void proj_mma_kernel()
{
    extern __shared__ uint32_t gsm[];
    const int which = blockIdx.z >> 2;
    const int b     = blockIdx.z & 3;
    const int t0    = blockIdx.x * 128;
    const int n0    = blockIdx.y * 128;
    const float* X  = g_X + ((size_t)which * B_ + b) * T_ * E_ + (size_t)t0 * E_;
    const float* Bm = g_Wt + (size_t)which * E_ * E_ + (size_t)n0 * E_;

    float C[2][8][4];
    gemm_tile_async(X, Bm, gsm, C);

    const float scale = (which == 0) ? 0.03125f : 1.0f;
    const int lane = threadIdx.x & 31, wid = threadIdx.x >> 5;
    const int g = lane >> 2, tg = lane & 3;
    const int mw = (wid & 3) * 32, nw = (wid >> 2) * 64;
    float* Cp = g_projF + ((size_t)which * B_ + b) * T_ * E_;

#pragma unroll
    for (int i = 0; i < 2; i++) {
        size_t r = (size_t)(t0 + mw + 16 * i + g);
#pragma unroll
        for (int j = 0; j < 8; j++) {
            int cc = n0 + nw + 8 * j + 2 * tg;
            float2 v0 = {rnd_tf(C[i][j][0] * scale), rnd_tf(C[i][j][1] * scale)};
            float2 v1 = {rnd_tf(C[i][j][2] * scale), rnd_tf(C[i][j][3] * scale)};
            *(float2*)&Cp[r * E_ + cc] = v0;
            *(float2*)&Cp[(r + 8) * E_ + cc] = v1;
        }
    }
}

// ============================================================================
// Output projection: out = g_attn @ g_Wp^T + bp (fp32 epilogue).
// ============================================================================
__global__ __launch_bounds__(256, 2) void outproj_mma_kernel(
    const float* __restrict__ bp, float* __restrict__ out)
{
    extern __shared__ uint32_t gsm[];
    const int m0 = blockIdx.x * 128;
    const int n0 = blockIdx.y * 128;

    float C[2][8][4];
    gemm_tile_async(g_attn + (size_t)m0 * E_, g_Wp + (size_t)n0 * E_, gsm, C);

    const int lane = threadIdx.x & 31, wid = threadIdx.x >> 5;
    const int g = lane >> 2, tg = lane & 3;
    const int mw = (wid & 3) * 32, nw = (wid >> 2) * 64;

#pragma unroll
    for (int i = 0; i < 2; i++) {
        size_t r = (size_t)(m0 + mw + 16 * i + g);
#pragma unroll
        for (int j = 0; j < 8; j++) {
            int cc = n0 + nw + 8 * j + 2 * tg;
            float2 bv = *(const float2*)&bp[cc];
            float2 v0 = {C[i][j][0] + bv.x, C[i][j][1] + bv.y};
            float2 v1 = {C[i][j][2] + bv.x, C[i][j][3] + bv.y};
            *(float2*)&out[r * E_ + cc] = v0;
            *(float2*)&out[(r + 8) * E_ + cc] = v1;
        }
    }
}

// ============================================================================
// Causal flash attention, tf32 mma. 3 CTAs/SM target:
// K double-buffered (cp.async), V single-buffered (issued post-PV, overlaps
// next iter's S+softmax), Ps stride 68. smem = 69 KB.
// grid (T/64, B*H), 128 threads (4 warps).
// ============================================================================
#define KLD 68
#define VLD 72
#define PLD 68
#define KS_W (64 * KLD)     // 4352 words per K stage
#define VS_W (64 * VLD)     // 4608 words (single V stage)
#define PS_W (64 * PLD)     // 4352 words
#define FLASH_SMEM_BYTES ((2 * KS_W + VS_W + PS_W) * 4)   // 70656

__global__ __launch_bounds__(128, 3) void flash_mma_kernel()
{
    extern __shared__ uint32_t smf[];
    uint32_t* Ks2 = smf;                    // [2][64][KLD]
    uint32_t* Vs  = smf + 2 * KS_W;         // [64][VLD]
    uint32_t* Ps  = smf + 2 * KS_W + VS_W;  // [64][PLD] (also Q staging)

    const int bh = blockIdx.y, b = bh >> 4, h = bh & 15;
    const int qt = gridDim.x - 1 - blockIdx.x;   // longest CTAs first
    const int tid = threadIdx.x, wid = tid >> 5, lane = tid & 31;
    const int g = lane >> 2, tg = lane & 3;

    const float* Q = g_projF + ((size_t)0 * B_ + b) * T_ * E_ +
                     (size_t)(qt * 64) * E_ + h * 64;
    const float* K = g_projF + ((size_t)1 * B_ + b) * T_ * E_ + h * 64;
    const float* V = g_projF + ((size_t)2 * B_ + b) * T_ * E_ + h * 64;

    const uint32_t ks_u = smem_u32(Ks2);
    const uint32_t vs_u = smem_u32(Vs);

    auto issueK = [&](int kt, int s) {
        const uint32_t kb = ks_u + (uint32_t)s * KS_W * 4;
#pragma unroll
        for (int u = 0; u < 8; u++) {
            int idx = tid + (u << 7);
            int r = idx >> 4, q4 = (idx & 15) << 2;
            cp16(kb + (uint32_t)(r * KLD + q4) * 4,
                 K + (size_t)(kt * 64 + r) * E_ + q4);
        }
        CP_COMMIT;
    };
    auto issueV = [&](int kt) {
#pragma unroll
        for (int u = 0; u < 8; u++) {
            int idx = tid + (u << 7);
            int r = idx >> 4, q4 = (idx & 15) << 2;
            cp16(vs_u + (uint32_t)(r * VLD + q4) * 4,
                 V + (size_t)(kt * 64 + r) * E_ + q4);
        }
        CP_COMMIT;
    };

    // prologue: K0, V0, K1 in flight
    issueK(0, 0);
    issueV(0);
    if (qt >= 1) issueK(1, 1);

    // stage Q -> Ps (raw bits, already tf32-exact), build A-fragments
#pragma unroll
    for (int u = 0; u < 8; u++) {
        int idx = tid + (u << 7);
        int r = idx >> 4, q4 = (idx & 15) << 2;
        *(float4*)&Ps[r * PLD + q4] = *(const float4*)&Q[(size_t)r * E_ + q4];
    }
    __syncthreads();

    uint32_t qf[8][4];
    {
        int rb = (wid * 16 + g) * PLD;
#pragma unroll
        for (int ks = 0; ks < 8; ks++) {
            qf[ks][0] = Ps[rb + tg + 8 * ks];
            qf[ks][1] = Ps[rb + 8 * PLD + tg + 8 * ks];
            qf[ks][2] = Ps[rb + tg + 4 + 8 * ks];
            qf[ks][3] = Ps[rb + 8 * PLD + tg + 4 + 8 * ks];
        }
    }

    float O[8][4];
#pragma unroll
    for (int j = 0; j < 8; j++)
#pragma unroll
        for (int p = 0; p < 4; p++) O[j][p] = 0.f;
    float m0 = -INFINITY, m1 = -INFINITY, l0 = 0.f, l1 = 0.f;

    for (int kt = 0; kt <= qt; kt++) {
        if (kt < qt) { CP_WAIT1; } else { CP_WAIT0; }
        __syncthreads();   // K(kt), V(kt) visible; prior compute complete

        const uint32_t* Ks = Ks2 + (size_t)(kt & 1) * KS_W;

        // ---- S = Q @ K^T ----
        float S[8][4];
#pragma unroll
        for (int j = 0; j < 8; j++)
#pragma unroll
            for (int p = 0; p < 4; p++) S[j][p] = 0.f;

#pragma unroll
        for (int ks = 0; ks < 8; ks++) {
            uint32_t bf[8][2];
#pragma unroll
            for (int j = 0; j < 8; j++) {
                int base = (g + 8 * j) * KLD + tg + 8 * ks;
                bf[j][0] = Ks[base];
                bf[j][1] = Ks[base + 4];
            }
#pragma unroll
            for (int j = 0; j < 8; j++) mma8(S[j], qf[ks], bf[j]);
        }

        // ---- causal mask on diagonal tile ----
        if (kt == qt) {
            int r0 = wid * 16 + g, r1 = r0 + 8;
#pragma unroll
            for (int j = 0; j < 8; j++) {
                int c0 = 8 * j + 2 * tg;
                if (c0 > r0) S[j][0] = -INFINITY;
                if (c0 + 1 > r0) S[j][1] = -INFINITY;
                if (c0 > r1) S[j][2] = -INFINITY;
                if (c0 + 1 > r1) S[j][3] = -INFINITY;
            }
        }

        // ---- online softmax ----
        float rm0 = -INFINITY, rm1 = -INFINITY;
#pragma unroll
        for (int j = 0; j < 8; j++) {
            rm0 = fmaxf(rm0, fmaxf(S[j][0], S[j][1]));
            rm1 = fmaxf(rm1, fmaxf(S[j][2], S[j][3]));
        }
        rm0 = fmaxf(rm0, __shfl_xor_sync(0xffffffffu, rm0, 1));
        rm0 = fmaxf(rm0, __shfl_xor_sync(0xffffffffu, rm0, 2));
        rm1 = fmaxf(rm1, __shfl_xor_sync(0xffffffffu, rm1, 1));
        rm1 = fmaxf(rm1, __shfl_xor_sync(0xffffffffu, rm1, 2));

        float mn0 = fmaxf(m0, rm0), mn1 = fmaxf(m1, rm1);
        float a0 = __expf(m0 - mn0), a1 = __expf(m1 - mn1);
        float s0 = 0.f, s1 = 0.f;
#pragma unroll
        for (int j = 0; j < 8; j++) {
            S[j][0] = __expf(S[j][0] - mn0);
            S[j][1] = __expf(S[j][1] - mn0);
            S[j][2] = __expf(S[j][2] - mn1);
            S[j][3] = __expf(S[j][3] - mn1);
            s0 += S[j][0] + S[j][1];
            s1 += S[j][2] + S[j][3];
        }
        s0 += __shfl_xor_sync(0xffffffffu, s0, 1);
        s0 += __shfl_xor_sync(0xffffffffu, s0, 2);
        s1 += __shfl_xor_sync(0xffffffffu, s1, 1);
        s1 += __shfl_xor_sync(0xffffffffu, s1, 2);
        l0 = l0 * a0 + s0;
        l1 = l1 * a1 + s1;
        m0 = mn0;
        m1 = mn1;
#pragma unroll
        for (int j = 0; j < 8; j++) {
            O[j][0] *= a0; O[j][1] *= a0;
            O[j][2] *= a1; O[j][3] *= a1;
        }

        // ---- stage P into per-warp-private smem strip (round to tf32) ----
        {
            int pr0 = (wid * 16 + g) * PLD, pr1 = pr0 + 8 * PLD;
#pragma unroll
            for (int j = 0; j < 8; j++) {
                int cc = 8 * j + 2 * tg;
                uint2 p0 = {f2tf(S[j][0]), f2tf(S[j][1])};
                uint2 p1 = {f2tf(S[j][2]), f2tf(S[j][3])};
                *(uint2*)&Ps[pr0 + cc] = p0;
                *(uint2*)&Ps[pr1 + cc] = p1;
            }
        }
        __syncwarp();

        // ---- O += P @ V ----
#pragma unroll
        for (int ks = 0; ks < 8; ks++) {
            uint32_t af[4], bf[8][2];
            int base = (wid * 16 + g) * PLD + tg + 8 * ks;
            af[0] = Ps[base];
            af[1] = Ps[base + 8 * PLD];
            af[2] = Ps[base + 4];
            af[3] = Ps[base + 8 * PLD + 4];
#pragma unroll
            for (int j = 0; j < 8; j++) {
                int vb = (8 * ks + tg) * VLD + g + 8 * j;
                bf[j][0] = Vs[vb];
                bf[j][1] = Vs[vb + 4 * VLD];
            }
#pragma unroll
            for (int j = 0; j < 8; j++) mma8(O[j], af, bf[j]);
        }

        // ---- refill single V buffer + next K stage (overlap next S phase) ----
        __syncthreads();   // all warps finished reading Vs
        if (kt + 1 <= qt) {
            issueV(kt + 1);
            if (kt + 2 <= qt) issueK(kt + 2, (kt + 2) & 1);
        }
    }

    // ---- epilogue: normalize, round to tf32, write [B,T,E] ----
    float inv0 = 1.f / l0, inv1 = 1.f / l1;
    float* outp = g_attn + ((size_t)b * T_ + (size_t)qt * 64 + wid * 16 + g) * E_ + h * 64;
#pragma unroll
    for (int j = 0; j < 8; j++) {
        int cc = 8 * j + 2 * tg;
        float2 v0 = {rnd_tf(O[j][0] * inv0), rnd_tf(O[j][1] * inv0)};
        float2 v1 = {rnd_tf(O[j][2] * inv1), rnd_tf(O[j][3] * inv1)};
        *(float2*)&outp[cc] = v0;
        *(float2*)(outp + 8 * E_ + cc) = v1;
    }
}

// ============================================================================
extern "C" void kernel_launch(void* const* d_in, const int* in_sizes, int n_in,
                              void* d_out, int out_size)
{
    // metadata order: k, q, v, mask, Wk, Wq, Wv, Wp, bp
    const float* k  = (const float*)d_in[0];
    const float* q  = (const float*)d_in[1];
    const float* v  = (const float*)d_in[2];
    const float* Wk = (const float*)d_in[4];
    const float* Wq = (const float*)d_in[5];
    const float* Wv = (const float*)d_in[6];
    const float* Wp = (const float*)d_in[7];
    const float* bp = (const float*)d_in[8];
    float* out = (float*)d_out;

    cudaFuncSetAttribute(proj_mma_kernel,
                         cudaFuncAttributeMaxDynamicSharedMemorySize, GEMM_SMEM_BYTES);
    cudaFuncSetAttribute(outproj_mma_kernel,
                         cudaFuncAttributeMaxDynamicSharedMemorySize, GEMM_SMEM_BYTES);
    cudaFuncSetAttribute(flash_mma_kernel,
                         cudaFuncAttributeMaxDynamicSharedMemorySize, FLASH_SMEM_BYTES);

    cvt_round_kernel<<<dim3(8192, 4), 256>>>(q, k, v, Wp);

    transpose_w_kernel<<<dim3(E_ / 64, H_, 3), 256>>>(Wq, Wk, Wv);

    proj_mma_kernel<<<dim3(T_ / 128, E_ / 128, 12), 256, GEMM_SMEM_BYTES>>>();

    flash_mma_kernel<<<dim3(T_ / 64, B_ * H_), 128, FLASH_SMEM_BYTES>>>();

    outproj_mma_kernel<<<dim3((B_ * T_) / 128, E_ / 128), 256, GEMM_SMEM_BYTES>>>(bp, out);
}